// round 2
// baseline (speedup 1.0000x reference)
#include <cuda_runtime.h>
#include <cstdint>

#define N 2048
#define D 128
#define E 16384
#define OUTCOLS (2 * E)

// Scratch (device globals — no allocation allowed in kernel_launch)
__device__ float g_u[D];
__device__ float g_sj[N];
__device__ float g_ej[N];
__device__ float g_Z[N];
__device__ int   g_is64;   // 1 if edge_indices buffer is int64, 0 if int32

// ---------------------------------------------------------------------------
// Kernel 0: detect edge_indices dtype. If the buffer is int64, every value
// read as u64 is < N (indices in [0, 2048)). If it is int32, a u64 read packs
// two random int32 indices -> high word almost surely nonzero -> >= N.
// ---------------------------------------------------------------------------
__global__ void k_detect(const unsigned long long* __restrict__ e64) {
    int ok = 1;
#pragma unroll
    for (int i = 0; i < 64; i++) {
        if (e64[i] >= (unsigned long long)N) { ok = 0; break; }
    }
    g_is64 = ok;
}

// ---------------------------------------------------------------------------
// Kernel 1: zero the 256 MB output. This is the runtime floor.
// ---------------------------------------------------------------------------
__global__ void k_zero(float4* __restrict__ out, size_t n4) {
    size_t i = (size_t)blockIdx.x * blockDim.x + threadIdx.x;
    size_t stride = (size_t)gridDim.x * blockDim.x;
    const float4 z = make_float4(0.f, 0.f, 0.f, 0.f);
    for (; i < n4; i += stride) out[i] = z;
}

// ---------------------------------------------------------------------------
// Kernel 2: u[c] = sum_d W1[d, c] * W2[0, D + d]      (128 threads, 1 block)
// ---------------------------------------------------------------------------
__global__ void k_u(const float* __restrict__ W1, const float* __restrict__ W2) {
    int c = threadIdx.x;  // 0..127
    float acc = 0.f;
#pragma unroll 8
    for (int d = 0; d < D; d++) acc += W1[d * D + c] * W2[D + d];
    g_u[c] = acc;
}

// ---------------------------------------------------------------------------
// Kernel 3: s_j[row] = X_n[row, :] . u      (one warp per row)
// ---------------------------------------------------------------------------
__global__ void k_sj(const float* __restrict__ X) {
    __shared__ float us[D];
    int tid = threadIdx.x;
    if (tid < D) us[tid] = g_u[tid];
    __syncthreads();

    int warp = tid >> 5;
    int lane = tid & 31;
    int row = blockIdx.x * (blockDim.x >> 5) + warp;
    if (row >= N) return;

    const float* xr = X + (size_t)row * D;
    float acc = 0.f;
#pragma unroll
    for (int c = lane; c < D; c += 32) acc += xr[c] * us[c];
#pragma unroll
    for (int o = 16; o; o >>= 1) acc += __shfl_down_sync(0xffffffffu, acc, o);
    if (lane == 0) g_sj[row] = acc;
}

// ---------------------------------------------------------------------------
// Kernel 4: global max of s_j, then e_j = exp(s_j - m)   (1 block, 1024 thr)
// ---------------------------------------------------------------------------
__global__ void k_maxexp() {
    __shared__ float sm[1024];
    int t = threadIdx.x;
    float a = g_sj[t];
    float b = g_sj[t + 1024];
    sm[t] = fmaxf(a, b);
    __syncthreads();
#pragma unroll
    for (int o = 512; o; o >>= 1) {
        if (t < o) sm[t] = fmaxf(sm[t], sm[t + o]);
        __syncthreads();
    }
    float m = sm[0];
    g_ej[t]        = expf(a - m);
    g_ej[t + 1024] = expf(b - m);
}

// ---------------------------------------------------------------------------
// Kernel 5: Z[row] = sum_k (adj[row,k] > 0) ? e_j[k] : 0   (block per row)
// ---------------------------------------------------------------------------
__global__ void k_Z(const int* __restrict__ adj) {
    __shared__ float ej[N];
    __shared__ float red[256];
    int t = threadIdx.x;  // 256 threads
    for (int k = t; k < N; k += 256) ej[k] = g_ej[k];
    __syncthreads();

    int row = blockIdx.x;
    const int4* ar = (const int4*)(adj + (size_t)row * N);
    float acc = 0.f;
#pragma unroll
    for (int k = t; k < N / 4; k += 256) {
        int4 v = ar[k];
        int base = k * 4;
        if (v.x > 0) acc += ej[base + 0];
        if (v.y > 0) acc += ej[base + 1];
        if (v.z > 0) acc += ej[base + 2];
        if (v.w > 0) acc += ej[base + 3];
    }
    red[t] = acc;
    __syncthreads();
#pragma unroll
    for (int o = 128; o; o >>= 1) {
        if (t < o) red[t] += red[t + o];
        __syncthreads();
    }
    if (t == 0) g_Z[row] = red[0];
}

// ---------------------------------------------------------------------------
// Kernel 6: scatter the 2*E attention values into the zeroed output
//   a_p = attention[dst, src] -> out[dst, c]
//   a_c = attention[src, dst] -> out[src, c + E]
// Handles both int64 and int32 edge buffers; bounds-guards so a wrong dtype
// guess can never produce an illegal access.
// ---------------------------------------------------------------------------
__global__ void k_scatter(const void* __restrict__ edges,
                          const int* __restrict__ adj,
                          float* __restrict__ out) {
    int c = blockIdx.x * blockDim.x + threadIdx.x;
    if (c >= E) return;

    int src, dst;
    if (g_is64) {
        const long long* e = (const long long*)edges;
        src = (int)e[c];
        dst = (int)e[E + c];
    } else {
        const int* e = (const int*)edges;
        src = e[c];
        dst = e[E + c];
    }
    if ((unsigned)src >= (unsigned)N || (unsigned)dst >= (unsigned)N) return;

    float ap = (adj[(size_t)dst * N + src] > 0) ? g_ej[src] / g_Z[dst] : 0.f;
    float ac = (adj[(size_t)src * N + dst] > 0) ? g_ej[dst] / g_Z[src] : 0.f;

    out[(size_t)dst * OUTCOLS + c]     = ap;
    out[(size_t)src * OUTCOLS + c + E] = ac;
}

// ---------------------------------------------------------------------------
// kernel_launch
// Inputs (metadata order): X_n [N,D] f32, edge_indices [2,E] i64-or-i32,
//                          adj [N,N] i32, W1 [D,D] f32, W2 [1,2D] f32
// Output: atten_matrix [N, 2E] f32
// ---------------------------------------------------------------------------
extern "C" void kernel_launch(void* const* d_in, const int* in_sizes, int n_in,
                              void* d_out, int out_size) {
    const float* X     = (const float*)d_in[0];
    const void*  edges = d_in[1];
    const int*   adj   = (const int*)d_in[2];
    const float* W1    = (const float*)d_in[3];
    const float* W2    = (const float*)d_in[4];
    float*       out   = (float*)d_out;

    // 0) sniff edge index dtype
    k_detect<<<1, 1>>>((const unsigned long long*)edges);

    // 1) zero the output (dominant cost: 256 MB store)
    size_t n4 = (size_t)N * OUTCOLS / 4;
    k_zero<<<32768, 256>>>((float4*)out, n4);

    // 2) u = W1^T @ W2[0, D:]
    k_u<<<1, D>>>(W1, W2);

    // 3) s_j = X_n @ u  (one warp per row, 8 rows per block)
    k_sj<<<N / 8, 256>>>(X);

    // 4) global max + exp
    k_maxexp<<<1, 1024>>>();

    // 5) per-row masked denominator Z
    k_Z<<<N, 256>>>(adj);

    // 6) scatter edge attention values
    k_scatter<<<E / 256, 256>>>(edges, adj, out);
}

// round 3
// speedup vs baseline: 1.1684x; 1.1684x over previous
#include <cuda_runtime.h>
#include <cstdint>

#define N 2048
#define D 128
#define E 16384
#define OUTCOLS (2 * E)

// Scratch (device globals — no allocation in kernel_launch)
__device__ float g_sj[N];
__device__ float g_ej[N];
__device__ float g_Z[N];
__device__ int   g_src_i[E];
__device__ int   g_dst_i[E];
__device__ float g_ap[E];
__device__ float g_ac[E];

// ---------------------------------------------------------------------------
// Kernel A: detect edge dtype (i64 vs i32) and convert to int32, clamped to
// [0, N) so downstream can never IMA.
// ---------------------------------------------------------------------------
__global__ void k_edgeconv(const void* __restrict__ edges) {
    __shared__ int is64s;
    if (threadIdx.x == 0) {
        const unsigned long long* e64 = (const unsigned long long*)edges;
        int ok = 1;
        for (int i = 0; i < 64; i++)
            if (e64[i] >= (unsigned long long)N) { ok = 0; break; }
        is64s = ok;
    }
    __syncthreads();
    int i = blockIdx.x * blockDim.x + threadIdx.x;
    int stride = blockDim.x * gridDim.x;
    if (is64s) {
        const long long* e = (const long long*)edges;
        for (; i < 2 * E; i += stride) {
            int v = (int)e[i];
            if ((unsigned)v >= (unsigned)N) v = 0;
            if (i < E) g_src_i[i] = v; else g_dst_i[i - E] = v;
        }
    } else {
        const int* e = (const int*)edges;
        for (; i < 2 * E; i += stride) {
            int v = e[i];
            if ((unsigned)v >= (unsigned)N) v = 0;
            if (i < E) g_src_i[i] = v; else g_dst_i[i - E] = v;
        }
    }
}

// ---------------------------------------------------------------------------
// Kernel B: fused u = W1^T @ W2[0,D:]  then  s_j[row] = X[row,:] . u
// 64 blocks x 256 threads; each block redundantly computes u (16K FMA, free),
// then 8 warps handle 32 rows (4 rows/warp).
// ---------------------------------------------------------------------------
__global__ void k_pre(const float* __restrict__ X,
                      const float* __restrict__ W1,
                      const float* __restrict__ W2) {
    __shared__ float w2s[D];
    __shared__ float us[D];
    int t = threadIdx.x;
    if (t < D) w2s[t] = W2[D + t];
    __syncthreads();
    if (t < D) {
        float acc = 0.f;
#pragma unroll 8
        for (int d = 0; d < D; d++) acc += W1[d * D + t] * w2s[d];
        us[t] = acc;
    }
    __syncthreads();

    int warp = t >> 5, lane = t & 31;
#pragma unroll
    for (int rr = 0; rr < 4; rr++) {
        int row = blockIdx.x * 32 + warp * 4 + rr;
        const float* xr = X + (size_t)row * D;
        float acc = 0.f;
#pragma unroll
        for (int c = lane; c < D; c += 32) acc += xr[c] * us[c];
#pragma unroll
        for (int o = 16; o; o >>= 1) acc += __shfl_down_sync(0xffffffffu, acc, o);
        if (lane == 0) g_sj[row] = acc;
    }
}

// ---------------------------------------------------------------------------
// Kernel C: global max of s_j then e_j = exp(s_j - m)   (1 block, 1024 thr)
// ---------------------------------------------------------------------------
__global__ void k_maxexp() {
    __shared__ float sm[1024];
    int t = threadIdx.x;
    float a = g_sj[t];
    float b = g_sj[t + 1024];
    sm[t] = fmaxf(a, b);
    __syncthreads();
#pragma unroll
    for (int o = 512; o; o >>= 1) {
        if (t < o) sm[t] = fmaxf(sm[t], sm[t + o]);
        __syncthreads();
    }
    float m = sm[0];
    g_ej[t]        = expf(a - m);
    g_ej[t + 1024] = expf(b - m);
}

// ---------------------------------------------------------------------------
// Kernel D: Z[row] = sum_k (adj[row,k] > 0) ? e_j[k] : 0   (block per row)
// ---------------------------------------------------------------------------
__global__ void k_Z(const int* __restrict__ adj) {
    __shared__ float ej[N];
    __shared__ float red[256];
    int t = threadIdx.x;
    for (int k = t; k < N; k += 256) ej[k] = g_ej[k];
    __syncthreads();

    int row = blockIdx.x;
    const int4* ar = (const int4*)(adj + (size_t)row * N);
    float acc = 0.f;
#pragma unroll
    for (int k = t; k < N / 4; k += 256) {
        int4 v = ar[k];
        int base = k * 4;
        if (v.x > 0) acc += ej[base + 0];
        if (v.y > 0) acc += ej[base + 1];
        if (v.z > 0) acc += ej[base + 2];
        if (v.w > 0) acc += ej[base + 3];
    }
    red[t] = acc;
    __syncthreads();
#pragma unroll
    for (int o = 128; o; o >>= 1) {
        if (t < o) red[t] += red[t + o];
        __syncthreads();
    }
    if (t == 0) g_Z[row] = red[0];
}

// ---------------------------------------------------------------------------
// Kernel E: per-edge attention values
//   ap[c] = attention[dst, src],  ac[c] = attention[src, dst]
// ---------------------------------------------------------------------------
__global__ void k_edge(const int* __restrict__ adj) {
    int c = blockIdx.x * blockDim.x + threadIdx.x;
    if (c >= E) return;
    int src = g_src_i[c];
    int dst = g_dst_i[c];
    g_ap[c] = (adj[(size_t)dst * N + src] > 0) ? g_ej[src] / g_Z[dst] : 0.f;
    g_ac[c] = (adj[(size_t)src * N + dst] > 0) ? g_ej[dst] / g_Z[src] : 0.f;
}

// ---------------------------------------------------------------------------
// Kernel F: single-pass 256 MB output write.
//   out[r, c]     = (dst[c] == r) ? ap[c] : 0      for c <  E
//   out[r, E+c]   = (src[c] == r) ? ac[c] : 0      for c <  E
// Edge-index / value arrays are 64 KB each -> L1/L2 resident broadcast reads.
// Streaming stores (.cs) — output >> L2, don't thrash the cache.
// grid = (4, N), 512 threads; each block writes 2048 float4 (32 KB).
// ---------------------------------------------------------------------------
__global__ void __launch_bounds__(512) k_write(float4* __restrict__ out) {
    int r = blockIdx.y;
    const int4*   d4  = (const int4*)g_dst_i;
    const int4*   s4  = (const int4*)g_src_i;
    const float4* ap4 = (const float4*)g_ap;
    const float4* ac4 = (const float4*)g_ac;

    size_t rowbase = (size_t)r * (OUTCOLS / 4);
    int base = blockIdx.x * 2048;

#pragma unroll
    for (int i = 0; i < 4; i++) {
        int col4 = base + i * 512 + threadIdx.x;   // [0, 8192)
        float4 v;
        if (col4 < E / 4) {
            int4   d = d4[col4];
            float4 a = ap4[col4];
            v.x = (d.x == r) ? a.x : 0.f;
            v.y = (d.y == r) ? a.y : 0.f;
            v.z = (d.z == r) ? a.z : 0.f;
            v.w = (d.w == r) ? a.w : 0.f;
        } else {
            int j = col4 - E / 4;
            int4   s = s4[j];
            float4 a = ac4[j];
            v.x = (s.x == r) ? a.x : 0.f;
            v.y = (s.y == r) ? a.y : 0.f;
            v.z = (s.z == r) ? a.z : 0.f;
            v.w = (s.w == r) ? a.w : 0.f;
        }
        __stcs(&out[rowbase + col4], v);
    }
}

// ---------------------------------------------------------------------------
// kernel_launch
// Inputs: X_n [N,D] f32, edge_indices [2,E] i64/i32, adj [N,N] i32,
//         W1 [D,D] f32, W2 [1,2D] f32.  Output: [N, 2E] f32.
// ---------------------------------------------------------------------------
extern "C" void kernel_launch(void* const* d_in, const int* in_sizes, int n_in,
                              void* d_out, int out_size) {
    const float* X     = (const float*)d_in[0];
    const void*  edges = d_in[1];
    const int*   adj   = (const int*)d_in[2];
    const float* W1    = (const float*)d_in[3];
    const float* W2    = (const float*)d_in[4];
    float*       out   = (float*)d_out;

    k_edgeconv<<<32, 256>>>(edges);
    k_pre<<<N / 32, 256>>>(X, W1, W2);
    k_maxexp<<<1, 1024>>>();
    k_Z<<<N, 256>>>(adj);
    k_edge<<<E / 256, 256>>>(adj);

    dim3 wgrid(4, N);
    k_write<<<wgrid, 512>>>((float4*)out);
}

// round 4
// speedup vs baseline: 1.2059x; 1.0321x over previous
#include <cuda_runtime.h>
#include <cstdint>

#define N 2048
#define D 128
#define E 16384
#define OUTCOLS (2 * E)

// Scratch (device globals — no allocation in kernel_launch)
__device__ float g_sj[N];
__device__ float g_ej[N];
__device__ float g_Z[N];
__device__ int   g_src_i[E];
__device__ int   g_dst_i[E];
__device__ float g_ap[E];
__device__ float g_ac[E];

// ---------------------------------------------------------------------------
// Kernel A: detect edge dtype (i64 vs i32) and convert to int32, clamped to
// [0, N) so downstream can never IMA.
// ---------------------------------------------------------------------------
__global__ void k_edgeconv(const void* __restrict__ edges) {
    __shared__ int is64s;
    if (threadIdx.x == 0) {
        const unsigned long long* e64 = (const unsigned long long*)edges;
        int ok = 1;
        for (int i = 0; i < 64; i++)
            if (e64[i] >= (unsigned long long)N) { ok = 0; break; }
        is64s = ok;
    }
    __syncthreads();
    int i = blockIdx.x * blockDim.x + threadIdx.x;
    int stride = blockDim.x * gridDim.x;
    if (is64s) {
        const long long* e = (const long long*)edges;
        for (; i < 2 * E; i += stride) {
            int v = (int)e[i];
            if ((unsigned)v >= (unsigned)N) v = 0;
            if (i < E) g_src_i[i] = v; else g_dst_i[i - E] = v;
        }
    } else {
        const int* e = (const int*)edges;
        for (; i < 2 * E; i += stride) {
            int v = e[i];
            if ((unsigned)v >= (unsigned)N) v = 0;
            if (i < E) g_src_i[i] = v; else g_dst_i[i - E] = v;
        }
    }
}

// ---------------------------------------------------------------------------
// Kernel B: fused u = W1^T @ W2[0,D:]  then  s_j[row] = X[row,:] . u
// ---------------------------------------------------------------------------
__global__ void k_pre(const float* __restrict__ X,
                      const float* __restrict__ W1,
                      const float* __restrict__ W2) {
    __shared__ float w2s[D];
    __shared__ float us[D];
    int t = threadIdx.x;
    if (t < D) w2s[t] = W2[D + t];
    __syncthreads();
    if (t < D) {
        float acc = 0.f;
#pragma unroll 8
        for (int d = 0; d < D; d++) acc += W1[d * D + t] * w2s[d];
        us[t] = acc;
    }
    __syncthreads();

    int warp = t >> 5, lane = t & 31;
#pragma unroll
    for (int rr = 0; rr < 4; rr++) {
        int row = blockIdx.x * 32 + warp * 4 + rr;
        const float* xr = X + (size_t)row * D;
        float acc = 0.f;
#pragma unroll
        for (int c = lane; c < D; c += 32) acc += xr[c] * us[c];
#pragma unroll
        for (int o = 16; o; o >>= 1) acc += __shfl_down_sync(0xffffffffu, acc, o);
        if (lane == 0) g_sj[row] = acc;
    }
}

// ---------------------------------------------------------------------------
// Kernel C: global max of s_j then e_j = exp(s_j - m)   (1 block, 1024 thr)
// ---------------------------------------------------------------------------
__global__ void k_maxexp() {
    __shared__ float sm[1024];
    int t = threadIdx.x;
    float a = g_sj[t];
    float b = g_sj[t + 1024];
    sm[t] = fmaxf(a, b);
    __syncthreads();
#pragma unroll
    for (int o = 512; o; o >>= 1) {
        if (t < o) sm[t] = fmaxf(sm[t], sm[t + o]);
        __syncthreads();
    }
    float m = sm[0];
    g_ej[t]        = expf(a - m);
    g_ej[t + 1024] = expf(b - m);
}

// ---------------------------------------------------------------------------
// Kernel D: Z[row] = sum_k (adj[row,k] > 0) ? e_j[k] : 0
// Warp-per-row, 8 rows per block (256 blocks x 256 threads).
// Each lane: 16 independent int4 loads (MLP=16 covers DRAM latency).
// ej staged in shared as float4 (LDS.128, conflict-free), amortized x8.
// Warp-shuffle reduce — no __syncthreads in the hot path.
// __ldcs on adj: pure streaming, keep it out of L2.
// ---------------------------------------------------------------------------
__global__ void __launch_bounds__(256) k_Z(const int* __restrict__ adj) {
    __shared__ float4 ej4[N / 4];
    int t = threadIdx.x;
    {
        const float4* src = (const float4*)g_ej;
        for (int k = t; k < N / 4; k += 256) ej4[k] = src[k];
    }
    __syncthreads();

    int warp = t >> 5, lane = t & 31;
    int row = blockIdx.x * 8 + warp;

    const int4* ar = (const int4*)(adj + (size_t)row * N);
    float acc = 0.f;
#pragma unroll
    for (int i = 0; i < 16; i++) {
        int k = lane + 32 * i;          // int4 index in [0, 512)
        int4   v = __ldcs(&ar[k]);
        float4 e = ej4[k];
        if (v.x > 0) acc += e.x;
        if (v.y > 0) acc += e.y;
        if (v.z > 0) acc += e.z;
        if (v.w > 0) acc += e.w;
    }
#pragma unroll
    for (int o = 16; o; o >>= 1) acc += __shfl_down_sync(0xffffffffu, acc, o);
    if (lane == 0) g_Z[row] = acc;
}

// ---------------------------------------------------------------------------
// Kernel E: per-edge attention values
//   ap[c] = attention[dst, src],  ac[c] = attention[src, dst]
// ---------------------------------------------------------------------------
__global__ void k_edge(const int* __restrict__ adj) {
    int c = blockIdx.x * blockDim.x + threadIdx.x;
    if (c >= E) return;
    int src = g_src_i[c];
    int dst = g_dst_i[c];
    g_ap[c] = (adj[(size_t)dst * N + src] > 0) ? g_ej[src] / g_Z[dst] : 0.f;
    g_ac[c] = (adj[(size_t)src * N + dst] > 0) ? g_ej[dst] / g_Z[src] : 0.f;
}

// ---------------------------------------------------------------------------
// Kernel F: single-pass 256 MB output write.
//   out[r, c]   = (dst[c] == r) ? ap[c] : 0      for c < E
//   out[r, E+c] = (src[c] == r) ? ac[c] : 0      for c < E
// Streaming stores; edge arrays (64 KB each) are L2-resident broadcasts.
// ---------------------------------------------------------------------------
__global__ void __launch_bounds__(512) k_write(float4* __restrict__ out) {
    int r = blockIdx.y;
    const int4*   d4  = (const int4*)g_dst_i;
    const int4*   s4  = (const int4*)g_src_i;
    const float4* ap4 = (const float4*)g_ap;
    const float4* ac4 = (const float4*)g_ac;

    size_t rowbase = (size_t)r * (OUTCOLS / 4);
    int base = blockIdx.x * 2048;

#pragma unroll
    for (int i = 0; i < 4; i++) {
        int col4 = base + i * 512 + threadIdx.x;   // [0, 8192)
        float4 v;
        if (col4 < E / 4) {
            int4   d = d4[col4];
            float4 a = ap4[col4];
            v.x = (d.x == r) ? a.x : 0.f;
            v.y = (d.y == r) ? a.y : 0.f;
            v.z = (d.z == r) ? a.z : 0.f;
            v.w = (d.w == r) ? a.w : 0.f;
        } else {
            int j = col4 - E / 4;
            int4   s = s4[j];
            float4 a = ac4[j];
            v.x = (s.x == r) ? a.x : 0.f;
            v.y = (s.y == r) ? a.y : 0.f;
            v.z = (s.z == r) ? a.z : 0.f;
            v.w = (s.w == r) ? a.w : 0.f;
        }
        __stcs(&out[rowbase + col4], v);
    }
}

// ---------------------------------------------------------------------------
// kernel_launch
// Inputs: X_n [N,D] f32, edge_indices [2,E] i64/i32, adj [N,N] i32,
//         W1 [D,D] f32, W2 [1,2D] f32.  Output: [N, 2E] f32.
// ---------------------------------------------------------------------------
extern "C" void kernel_launch(void* const* d_in, const int* in_sizes, int n_in,
                              void* d_out, int out_size) {
    const float* X     = (const float*)d_in[0];
    const void*  edges = d_in[1];
    const int*   adj   = (const int*)d_in[2];
    const float* W1    = (const float*)d_in[3];
    const float* W2    = (const float*)d_in[4];
    float*       out   = (float*)d_out;

    k_edgeconv<<<32, 256>>>(edges);
    k_pre<<<N / 32, 256>>>(X, W1, W2);
    k_maxexp<<<1, 1024>>>();
    k_Z<<<N / 8, 256>>>(adj);
    k_edge<<<E / 256, 256>>>(adj);

    dim3 wgrid(4, N);
    k_write<<<wgrid, 512>>>((float4*)out);
}

// round 5
// speedup vs baseline: 1.2091x; 1.0027x over previous
#include <cuda_runtime.h>
#include <cstdint>

#define N 2048
#define D 128
#define E 16384
#define OUTCOLS (2 * E)

// Scratch (device globals — no allocation in kernel_launch)
__device__ float g_sj[N];
__device__ float g_ej[N];
__device__ float g_Z[N];
__device__ int   g_src_i[E];
__device__ int   g_dst_i[E];
__device__ float g_ap[E];
__device__ float g_ac[E];

// ---------------------------------------------------------------------------
// Kernel A: detect edge dtype (i64 vs i32) and convert to int32, clamped to
// [0, N) so downstream can never IMA.
// ---------------------------------------------------------------------------
__global__ void k_edgeconv(const void* __restrict__ edges) {
    __shared__ int is64s;
    if (threadIdx.x == 0) {
        const unsigned long long* e64 = (const unsigned long long*)edges;
        int ok = 1;
        for (int i = 0; i < 64; i++)
            if (e64[i] >= (unsigned long long)N) { ok = 0; break; }
        is64s = ok;
    }
    __syncthreads();
    int i = blockIdx.x * blockDim.x + threadIdx.x;
    int stride = blockDim.x * gridDim.x;
    if (is64s) {
        const long long* e = (const long long*)edges;
        for (; i < 2 * E; i += stride) {
            int v = (int)e[i];
            if ((unsigned)v >= (unsigned)N) v = 0;
            if (i < E) g_src_i[i] = v; else g_dst_i[i - E] = v;
        }
    } else {
        const int* e = (const int*)edges;
        for (; i < 2 * E; i += stride) {
            int v = e[i];
            if ((unsigned)v >= (unsigned)N) v = 0;
            if (i < E) g_src_i[i] = v; else g_dst_i[i - E] = v;
        }
    }
}

// ---------------------------------------------------------------------------
// Kernel B: fused u = W1^T @ W2[0,D:]  then  s_j[row] = X[row,:] . u
// ---------------------------------------------------------------------------
__global__ void k_pre(const float* __restrict__ X,
                      const float* __restrict__ W1,
                      const float* __restrict__ W2) {
    __shared__ float w2s[D];
    __shared__ float us[D];
    int t = threadIdx.x;
    if (t < D) w2s[t] = W2[D + t];
    __syncthreads();
    if (t < D) {
        float acc = 0.f;
#pragma unroll 8
        for (int d = 0; d < D; d++) acc += W1[d * D + t] * w2s[d];
        us[t] = acc;
    }
    __syncthreads();

    int warp = t >> 5, lane = t & 31;
#pragma unroll
    for (int rr = 0; rr < 4; rr++) {
        int row = blockIdx.x * 32 + warp * 4 + rr;
        const float* xr = X + (size_t)row * D;
        float acc = 0.f;
#pragma unroll
        for (int c = lane; c < D; c += 32) acc += xr[c] * us[c];
#pragma unroll
        for (int o = 16; o; o >>= 1) acc += __shfl_down_sync(0xffffffffu, acc, o);
        if (lane == 0) g_sj[row] = acc;
    }
}

// ---------------------------------------------------------------------------
// Kernel C: global max of s_j then e_j = exp(s_j - m)   (1 block, 1024 thr)
// ---------------------------------------------------------------------------
__global__ void k_maxexp() {
    __shared__ float sm[1024];
    int t = threadIdx.x;
    float a = g_sj[t];
    float b = g_sj[t + 1024];
    sm[t] = fmaxf(a, b);
    __syncthreads();
#pragma unroll
    for (int o = 512; o; o >>= 1) {
        if (t < o) sm[t] = fmaxf(sm[t], sm[t + o]);
        __syncthreads();
    }
    float m = sm[0];
    g_ej[t]        = expf(a - m);
    g_ej[t + 1024] = expf(b - m);
}

// ---------------------------------------------------------------------------
// Kernel D: Z[row] = sum_k (adj[row,k] > 0) ? e_j[k] : 0
// ONE WARP PER BLOCK, one row per warp, 2048 blocks:
//  - 2048/148 SMs -> ~13.8 blocks/SM, max/mean imbalance ~1.5% (R4's 256-block
//    grid had 2-vs-1 block SMs -> 50% straggler penalty).
//  - no smem, no __syncthreads; ej read via __ldg (8 KB, L1-resident).
//  - 16 independent __ldcs int4 loads per lane (MLP=16), streaming adj
//    (no reuse, keep out of L2 ahead of the 256 MB store pass).
// ---------------------------------------------------------------------------
__global__ void __launch_bounds__(32) k_Z(const int* __restrict__ adj) {
    int lane = threadIdx.x;
    int row = blockIdx.x;

    const int4*   ar  = (const int4*)(adj + (size_t)row * N);
    const float4* ej4 = (const float4*)g_ej;

    float acc = 0.f;
#pragma unroll
    for (int i = 0; i < 16; i++) {
        int k = lane + 32 * i;          // int4 index in [0, 512)
        int4   v = __ldcs(&ar[k]);
        float4 e = __ldg(&ej4[k]);
        if (v.x > 0) acc += e.x;
        if (v.y > 0) acc += e.y;
        if (v.z > 0) acc += e.z;
        if (v.w > 0) acc += e.w;
    }
#pragma unroll
    for (int o = 16; o; o >>= 1) acc += __shfl_down_sync(0xffffffffu, acc, o);
    if (lane == 0) g_Z[row] = acc;
}

// ---------------------------------------------------------------------------
// Kernel E: per-edge attention values
//   ap[c] = attention[dst, src],  ac[c] = attention[src, dst]
// ---------------------------------------------------------------------------
__global__ void k_edge(const int* __restrict__ adj) {
    int c = blockIdx.x * blockDim.x + threadIdx.x;
    if (c >= E) return;
    int src = g_src_i[c];
    int dst = g_dst_i[c];
    g_ap[c] = (adj[(size_t)dst * N + src] > 0) ? g_ej[src] / g_Z[dst] : 0.f;
    g_ac[c] = (adj[(size_t)src * N + dst] > 0) ? g_ej[dst] / g_Z[src] : 0.f;
}

// ---------------------------------------------------------------------------
// Kernel F: single-pass 256 MB output write.
//   out[r, c]   = (dst[c] == r) ? ap[c] : 0      for c < E
//   out[r, E+c] = (src[c] == r) ? ac[c] : 0      for c < E
// Streaming stores; edge tables (128 KB total) are L1-resident broadcasts.
// ---------------------------------------------------------------------------
__global__ void __launch_bounds__(512) k_write(float4* __restrict__ out) {
    int r = blockIdx.y;
    const int4*   d4  = (const int4*)g_dst_i;
    const int4*   s4  = (const int4*)g_src_i;
    const float4* ap4 = (const float4*)g_ap;
    const float4* ac4 = (const float4*)g_ac;

    size_t rowbase = (size_t)r * (OUTCOLS / 4);
    int base = blockIdx.x * 2048;

#pragma unroll
    for (int i = 0; i < 4; i++) {
        int col4 = base + i * 512 + threadIdx.x;   // [0, 8192)
        float4 v;
        if (col4 < E / 4) {
            int4   d = d4[col4];
            float4 a = ap4[col4];
            v.x = (d.x == r) ? a.x : 0.f;
            v.y = (d.y == r) ? a.y : 0.f;
            v.z = (d.z == r) ? a.z : 0.f;
            v.w = (d.w == r) ? a.w : 0.f;
        } else {
            int j = col4 - E / 4;
            int4   s = s4[j];
            float4 a = ac4[j];
            v.x = (s.x == r) ? a.x : 0.f;
            v.y = (s.y == r) ? a.y : 0.f;
            v.z = (s.z == r) ? a.z : 0.f;
            v.w = (s.w == r) ? a.w : 0.f;
        }
        __stcs(&out[rowbase + col4], v);
    }
}

// ---------------------------------------------------------------------------
// kernel_launch
// Inputs: X_n [N,D] f32, edge_indices [2,E] i64/i32, adj [N,N] i32,
//         W1 [D,D] f32, W2 [1,2D] f32.  Output: [N, 2E] f32.
// ---------------------------------------------------------------------------
extern "C" void kernel_launch(void* const* d_in, const int* in_sizes, int n_in,
                              void* d_out, int out_size) {
    const float* X     = (const float*)d_in[0];
    const void*  edges = d_in[1];
    const int*   adj   = (const int*)d_in[2];
    const float* W1    = (const float*)d_in[3];
    const float* W2    = (const float*)d_in[4];
    float*       out   = (float*)d_out;

    k_edgeconv<<<32, 256>>>(edges);
    k_pre<<<N / 32, 256>>>(X, W1, W2);
    k_maxexp<<<1, 1024>>>();
    k_Z<<<N, 32>>>(adj);
    k_edge<<<E / 256, 256>>>(adj);

    dim3 wgrid(4, N);
    k_write<<<wgrid, 512>>>((float4*)out);
}